// round 3
// baseline (speedup 1.0000x reference)
#include <cuda_runtime.h>
#include <math.h>

#define B_   2
#define S_   2048
#define D_   2048
#define H_   16
#define HD_  128
#define M_   (B_ * S_)   // 4096 rows for all GEMMs

// ---------------------------------------------------------------------------
// Scratch (static device arrays; no allocation allowed).
// Referenced directly from kernels — no cudaGetSymbolAddress needed.
// ---------------------------------------------------------------------------
__device__ float g_q[(size_t)M_ * D_];
__device__ float g_k[(size_t)M_ * D_];
__device__ float g_v[(size_t)M_ * D_];
__device__ float g_ctx[(size_t)M_ * D_];

// ---------------------------------------------------------------------------
// SGEMM body: C[M,N] = A[M,K] @ W[K,N] + bias,  N = K = 2048
// 128x128 block tile, BK=8, 256 threads, 8x8 per-thread micro-tile.
// Register-prefetch double buffering: next global slab loaded into registers
// while the current smem tile is consumed.
// ---------------------------------------------------------------------------
__device__ __forceinline__ void sgemm_body(
    const float* __restrict__ A, const float* __restrict__ W,
    const float* __restrict__ bias, float* __restrict__ C)
{
    const int N = D_;
    const int K = D_;

    __shared__ float As[8][128];   // A tile, transposed on load
    __shared__ float Bs[8][128];   // W tile, natural layout

    const int tid  = threadIdx.x;
    const int bx   = blockIdx.x;   // N tile
    const int by   = blockIdx.y;   // M tile
    const int trow = tid >> 4;     // 0..15
    const int tcol = tid & 15;     // 0..15

    float acc[8][8];
#pragma unroll
    for (int i = 0; i < 8; i++)
#pragma unroll
        for (int j = 0; j < 8; j++) acc[i][j] = 0.0f;

    // load indices
    const int aRow = tid >> 1;          // 0..127
    const int aCol = (tid & 1) << 2;    // 0 or 4
    const int bRow = tid >> 5;          // 0..7
    const int bCol = (tid & 31) << 2;   // 0..124

    const float* Ag = A + (size_t)(by * 128 + aRow) * K + aCol;
    const float* Bg = W + (size_t)bRow * N + bx * 128 + bCol;

    // prologue fetch
    float4 av = *(const float4*)Ag;
    float4 bv = *(const float4*)Bg;

    for (int k0 = 0; k0 < K; k0 += 8) {
        As[aCol + 0][aRow] = av.x;
        As[aCol + 1][aRow] = av.y;
        As[aCol + 2][aRow] = av.z;
        As[aCol + 3][aRow] = av.w;
        *(float4*)&Bs[bRow][bCol] = bv;
        __syncthreads();

        // prefetch next slab while computing this one
        Ag += 8;
        Bg += (size_t)8 * N;
        if (k0 + 8 < K) {
            av = *(const float4*)Ag;
            bv = *(const float4*)Bg;
        }

#pragma unroll
        for (int k = 0; k < 8; k++) {
            float ra[8], rb[8];
            *(float4*)&ra[0] = *(const float4*)&As[k][trow * 8];
            *(float4*)&ra[4] = *(const float4*)&As[k][trow * 8 + 4];
            *(float4*)&rb[0] = *(const float4*)&Bs[k][tcol * 8];
            *(float4*)&rb[4] = *(const float4*)&Bs[k][tcol * 8 + 4];
#pragma unroll
            for (int i = 0; i < 8; i++)
#pragma unroll
                for (int j = 0; j < 8; j++)
                    acc[i][j] += ra[i] * rb[j];
        }
        __syncthreads();
    }

    // epilogue: add bias, float4 stores
    float4 bb0 = *(const float4*)&bias[bx * 128 + tcol * 8];
    float4 bb1 = *(const float4*)&bias[bx * 128 + tcol * 8 + 4];
#pragma unroll
    for (int i = 0; i < 8; i++) {
        size_t row = (size_t)(by * 128 + trow * 8 + i);
        float* Cr  = C + row * N + bx * 128 + tcol * 8;
        float4 o0, o1;
        o0.x = acc[i][0] + bb0.x;  o0.y = acc[i][1] + bb0.y;
        o0.z = acc[i][2] + bb0.z;  o0.w = acc[i][3] + bb0.w;
        o1.x = acc[i][4] + bb1.x;  o1.y = acc[i][5] + bb1.y;
        o1.z = acc[i][6] + bb1.z;  o1.w = acc[i][7] + bb1.w;
        *(float4*)&Cr[0] = o0;
        *(float4*)&Cr[4] = o1;
    }
}

// Fused QKV projection: blockIdx.z selects {Q, K, V} weight/bias/output.
__global__ __launch_bounds__(256, 1) void qkv_kernel(
    const float* __restrict__ x,
    const float* __restrict__ wq, const float* __restrict__ bq,
    const float* __restrict__ wk, const float* __restrict__ bk,
    const float* __restrict__ wv, const float* __restrict__ bv)
{
    const int z = blockIdx.z;
    const float* W = (z == 0) ? wq : (z == 1) ? wk : wv;
    const float* bb = (z == 0) ? bq : (z == 1) ? bk : bv;
    float* C = (z == 0) ? g_q : (z == 1) ? g_k : g_v;
    sgemm_body(x, W, bb, C);
}

// Output projection: reads g_ctx, writes harness d_out.
__global__ __launch_bounds__(256, 1) void proj_kernel(
    const float* __restrict__ wp, const float* __restrict__ bp,
    float* __restrict__ out)
{
    sgemm_body(g_ctx, wp, bp, out);
}

// ---------------------------------------------------------------------------
// Flash attention (causal), Br = Bc = 64, HD = 128, fp32.
// 256 threads: thread (ty,tx) = (tid/16, tid%16)
//   owns score rows   r = 4*ty + i  (i in 0..3)
//   score cols        c = tx + 16*j (j in 0..3)   -> strided, low conflicts
//   output cols       c = tx + 16*j (j in 0..7)
// Reads g_q/g_k/g_v, writes g_ctx. No pointer parameters.
// ---------------------------------------------------------------------------
#define KS_STRIDE 132   // 128 + 4 pad
#define PS_STRIDE 65    // 64 + 1 pad

__global__ __launch_bounds__(256, 1) void attn_kernel()
{
    extern __shared__ float sm[];
    float* Qs = sm;                       // 64 * 128
    float* Ks = Qs + 64 * HD_;            // 64 * 132
    float* Vs = Ks + 64 * KS_STRIDE;      // 64 * 128
    float* Ps = Vs + 64 * HD_;            // 64 * 65

    const int tid = threadIdx.x;
    const int ty  = tid >> 4;   // 0..15
    const int tx  = tid & 15;   // 0..15

    const int qb = blockIdx.x;          // query block (64 rows)
    const int b  = blockIdx.y >> 4;
    const int h  = blockIdx.y & 15;

    const float* Qb = g_q + (size_t)b * S_ * D_ + (size_t)h * HD_;
    const float* Kb = g_k + (size_t)b * S_ * D_ + (size_t)h * HD_;
    const float* Vb = g_v + (size_t)b * S_ * D_ + (size_t)h * HD_;
    float*       Ob = g_ctx + (size_t)b * S_ * D_ + (size_t)h * HD_;

    // load Q tile (64 x 128)
    for (int t = tid; t < 64 * 32; t += 256) {
        int r = t >> 5;
        int c = (t & 31) << 2;
        *(float4*)&Qs[r * HD_ + c] =
            *(const float4*)&Qb[(size_t)(qb * 64 + r) * D_ + c];
    }

    float acc[4][8];
#pragma unroll
    for (int i = 0; i < 4; i++)
#pragma unroll
        for (int j = 0; j < 8; j++) acc[i][j] = 0.0f;
    float mrow[4] = {-INFINITY, -INFINITY, -INFINITY, -INFINITY};
    float lrow[4] = {0.0f, 0.0f, 0.0f, 0.0f};

    const float scale = 0.08838834764831845f;  // 1/sqrt(128)

    __syncthreads();

    for (int kb = 0; kb <= qb; kb++) {
        // load K, V tiles (64 x 128 each)
        for (int t = tid; t < 64 * 32; t += 256) {
            int r = t >> 5;
            int c = (t & 31) << 2;
            *(float4*)&Ks[r * KS_STRIDE + c] =
                *(const float4*)&Kb[(size_t)(kb * 64 + r) * D_ + c];
            *(float4*)&Vs[r * HD_ + c] =
                *(const float4*)&Vb[(size_t)(kb * 64 + r) * D_ + c];
        }
        __syncthreads();

        // S = Q @ K^T  (per-thread 4x4)
        float s[4][4];
#pragma unroll
        for (int i = 0; i < 4; i++)
#pragma unroll
            for (int j = 0; j < 4; j++) s[i][j] = 0.0f;

#pragma unroll 4
        for (int kk = 0; kk < HD_; kk += 4) {
            float4 qv[4], kv[4];
#pragma unroll
            for (int i = 0; i < 4; i++)
                qv[i] = *(const float4*)&Qs[(4 * ty + i) * HD_ + kk];
#pragma unroll
            for (int j = 0; j < 4; j++)
                kv[j] = *(const float4*)&Ks[(tx + 16 * j) * KS_STRIDE + kk];
#pragma unroll
            for (int i = 0; i < 4; i++)
#pragma unroll
                for (int j = 0; j < 4; j++) {
                    s[i][j] += qv[i].x * kv[j].x;
                    s[i][j] += qv[i].y * kv[j].y;
                    s[i][j] += qv[i].z * kv[j].z;
                    s[i][j] += qv[i].w * kv[j].w;
                }
        }

        // scale + causal mask (only diagonal block needs masking)
        const bool diag = (kb == qb);
#pragma unroll
        for (int i = 0; i < 4; i++) {
            int qr = 4 * ty + i;
#pragma unroll
            for (int j = 0; j < 4; j++) {
                int kc = tx + 16 * j;
                float sv = s[i][j] * scale;
                if (diag && kc > qr) sv = -INFINITY;
                s[i][j] = sv;
            }
        }

        // online softmax per row (reduce over the 16-lane tx group)
#pragma unroll
        for (int i = 0; i < 4; i++) {
            float tmax = fmaxf(fmaxf(s[i][0], s[i][1]), fmaxf(s[i][2], s[i][3]));
#pragma unroll
            for (int o = 8; o >= 1; o >>= 1)
                tmax = fmaxf(tmax, __shfl_xor_sync(0xffffffffu, tmax, o));
            float mnew = fmaxf(mrow[i], tmax);
            float corr = __expf(mrow[i] - mnew);
            float rsum = 0.0f;
#pragma unroll
            for (int j = 0; j < 4; j++) {
                float p = __expf(s[i][j] - mnew);
                Ps[(4 * ty + i) * PS_STRIDE + tx + 16 * j] = p;
                rsum += p;
            }
#pragma unroll
            for (int o = 8; o >= 1; o >>= 1)
                rsum += __shfl_xor_sync(0xffffffffu, rsum, o);
            lrow[i] = lrow[i] * corr + rsum;
            mrow[i] = mnew;
#pragma unroll
            for (int j = 0; j < 8; j++) acc[i][j] *= corr;
        }
        __syncthreads();

        // O += P @ V
#pragma unroll 4
        for (int k = 0; k < 64; k++) {
            float pv[4], vv[8];
#pragma unroll
            for (int i = 0; i < 4; i++)
                pv[i] = Ps[(4 * ty + i) * PS_STRIDE + k];
#pragma unroll
            for (int j = 0; j < 8; j++)
                vv[j] = Vs[k * HD_ + tx + 16 * j];
#pragma unroll
            for (int i = 0; i < 4; i++)
#pragma unroll
                for (int j = 0; j < 8; j++)
                    acc[i][j] += pv[i] * vv[j];
        }
        __syncthreads();
    }

    // epilogue: normalize, write ctx in [b, s, h*HD + d] layout
#pragma unroll
    for (int i = 0; i < 4; i++) {
        float inv = 1.0f / lrow[i];
        size_t rowoff = (size_t)(qb * 64 + 4 * ty + i) * D_;
#pragma unroll
        for (int j = 0; j < 8; j++)
            Ob[rowoff + tx + 16 * j] = acc[i][j] * inv;
    }
}

// ---------------------------------------------------------------------------
// launch: 3 kernel launches, one attribute call. No other host API.
// ---------------------------------------------------------------------------
extern "C" void kernel_launch(void* const* d_in, const int* in_sizes, int n_in,
                              void* d_out, int out_size)
{
    const float* x  = (const float*)d_in[0];
    const float* wq = (const float*)d_in[1];
    const float* bq = (const float*)d_in[2];
    const float* wk = (const float*)d_in[3];
    const float* bk = (const float*)d_in[4];
    const float* wv = (const float*)d_in[5];
    const float* bv = (const float*)d_in[6];
    const float* wp = (const float*)d_in[7];
    const float* bp = (const float*)d_in[8];
    float* out = (float*)d_out;

    dim3 qkvgrid(D_ / 128, M_ / 128, 3);   // (16, 32, 3)
    qkv_kernel<<<qkvgrid, 256>>>(x, wq, bq, wk, bk, wv, bv);

    const int smem = (64 * HD_ + 64 * KS_STRIDE + 64 * HD_ + 64 * PS_STRIDE) *
                     (int)sizeof(float);  // ~113 KB
    cudaFuncSetAttribute(attn_kernel,
                         cudaFuncAttributeMaxDynamicSharedMemorySize, smem);
    dim3 agrid(S_ / 64, B_ * H_);          // (32, 32)
    attn_kernel<<<agrid, 256, smem>>>();

    dim3 pgrid(D_ / 128, M_ / 128);        // (16, 32)
    proj_kernel<<<pgrid, 256>>>(wp, bp, out);
}

// round 8
// speedup vs baseline: 1.2931x; 1.2931x over previous
#include <cuda_runtime.h>
#include <math.h>
#include <stdint.h>

#define B_   2
#define S_   2048
#define D_   2048
#define H_   16
#define HD_  128
#define M_   (B_ * S_)   // 4096

// ---------------------------------------------------------------------------
// Scratch (static device arrays; no allocation allowed)
// ---------------------------------------------------------------------------
__device__ float g_q[(size_t)M_ * D_];
__device__ float g_k[(size_t)M_ * D_];
__device__ float g_v[(size_t)M_ * D_];
__device__ float g_ctx[(size_t)M_ * D_];

// ---------------------------------------------------------------------------
// tf32 mma.sync helper (sm_80+ base ISA — works on plain sm_100 target)
// ---------------------------------------------------------------------------
__device__ __forceinline__ void mma_tf32(float* d, const uint32_t* a,
                                         const uint32_t* b) {
    asm volatile(
        "mma.sync.aligned.m16n8k8.row.col.f32.tf32.tf32.f32 "
        "{%0,%1,%2,%3}, {%4,%5,%6,%7}, {%8,%9}, {%0,%1,%2,%3};"
        : "+f"(d[0]), "+f"(d[1]), "+f"(d[2]), "+f"(d[3])
        : "r"(a[0]), "r"(a[1]), "r"(a[2]), "r"(a[3]), "r"(b[0]), "r"(b[1]));
}

__device__ __forceinline__ float tf32_hi(float x) {
    return __uint_as_float(__float_as_uint(x) & 0xFFFFE000u);
}
__device__ __forceinline__ uint32_t f2u(float x) { return __float_as_uint(x); }

// ---------------------------------------------------------------------------
// tf32x3 tensor-core GEMM: C[128x128 tile] = A[M,K] @ W[K,N] + bias
// 512 threads, 16 warps in 4x4 grid, warp tile 32x32, BK=32.
// Smem: A [128][36] hi/lo (stride 36: conflict-free quad-row frag loads),
//       B [32][136] hi/lo (stride 136: k-groups on disjoint bank octets).
// ---------------------------------------------------------------------------
#define ASTR 36
#define BSTR 136
#define OFF_AH 0
#define OFF_AL (128 * ASTR)                   // 4608
#define OFF_BH (2 * 128 * ASTR)               // 9216
#define OFF_BL (2 * 128 * ASTR + 32 * BSTR)   // 13568
#define GEMM_SMEM_F (2 * 128 * ASTR + 2 * 32 * BSTR)   // 17920 floats
#define GEMM_SMEM   (GEMM_SMEM_F * 4)                  // 71680 bytes

__device__ __forceinline__ void tc_gemm(
    const float* __restrict__ A, const float* __restrict__ W,
    const float* __restrict__ bias, float* __restrict__ C)
{
    extern __shared__ float smf[];
    float* Ah = smf + OFF_AH;
    float* Al = smf + OFF_AL;
    float* Bh = smf + OFF_BH;
    float* Bl = smf + OFF_BL;

    const int tid  = threadIdx.x;
    const int lane = tid & 31;
    const int warp = tid >> 5;
    const int l4   = lane >> 2;      // 0..7
    const int l2   = lane & 3;       // 0..3
    const int wm   = (warp >> 2) * 32;   // warp row offset 0..96
    const int wn   = (warp & 3) * 32;    // warp col offset 0..96
    const int bx   = blockIdx.x;
    const int by   = blockIdx.y;

    float acc[2][4][4];
#pragma unroll
    for (int t = 0; t < 2; t++)
#pragma unroll
        for (int n = 0; n < 4; n++)
#pragma unroll
            for (int r = 0; r < 4; r++) acc[t][n][r] = 0.0f;

    // global load indices (2 float4 slots each for A and B per thread)
    const int ar0 = tid >> 3,  ac0 = (tid & 7) * 4;
    const int ar1 = (tid + 512) >> 3, ac1 = ((tid + 512) & 7) * 4;
    const int br0 = tid >> 5,  bc0 = (tid & 31) * 4;
    const int br1 = (tid + 512) >> 5, bc1 = ((tid + 512) & 31) * 4;

    const float* Abase = A + (size_t)(by * 128) * D_;
    const float* Wbase = W + (size_t)bx * 128;

    float4 pa0 = *(const float4*)&Abase[(size_t)ar0 * D_ + ac0];
    float4 pa1 = *(const float4*)&Abase[(size_t)ar1 * D_ + ac1];
    float4 pb0 = *(const float4*)&Wbase[(size_t)br0 * D_ + bc0];
    float4 pb1 = *(const float4*)&Wbase[(size_t)br1 * D_ + bc1];

    for (int it = 0; it < 64; ++it) {
        // --- split + stage to smem ---
        {
            float4 h, l;
            h.x = tf32_hi(pa0.x); l.x = pa0.x - h.x;
            h.y = tf32_hi(pa0.y); l.y = pa0.y - h.y;
            h.z = tf32_hi(pa0.z); l.z = pa0.z - h.z;
            h.w = tf32_hi(pa0.w); l.w = pa0.w - h.w;
            *(float4*)&Ah[ar0 * ASTR + ac0] = h;
            *(float4*)&Al[ar0 * ASTR + ac0] = l;
            h.x = tf32_hi(pa1.x); l.x = pa1.x - h.x;
            h.y = tf32_hi(pa1.y); l.y = pa1.y - h.y;
            h.z = tf32_hi(pa1.z); l.z = pa1.z - h.z;
            h.w = tf32_hi(pa1.w); l.w = pa1.w - h.w;
            *(float4*)&Ah[ar1 * ASTR + ac1] = h;
            *(float4*)&Al[ar1 * ASTR + ac1] = l;
            h.x = tf32_hi(pb0.x); l.x = pb0.x - h.x;
            h.y = tf32_hi(pb0.y); l.y = pb0.y - h.y;
            h.z = tf32_hi(pb0.z); l.z = pb0.z - h.z;
            h.w = tf32_hi(pb0.w); l.w = pb0.w - h.w;
            *(float4*)&Bh[br0 * BSTR + bc0] = h;
            *(float4*)&Bl[br0 * BSTR + bc0] = l;
            h.x = tf32_hi(pb1.x); l.x = pb1.x - h.x;
            h.y = tf32_hi(pb1.y); l.y = pb1.y - h.y;
            h.z = tf32_hi(pb1.z); l.z = pb1.z - h.z;
            h.w = tf32_hi(pb1.w); l.w = pb1.w - h.w;
            *(float4*)&Bh[br1 * BSTR + bc1] = h;
            *(float4*)&Bl[br1 * BSTR + bc1] = l;
        }
        __syncthreads();

        // --- prefetch next slab ---
        if (it < 63) {
            const int k0 = (it + 1) * 32;
            pa0 = *(const float4*)&Abase[(size_t)ar0 * D_ + k0 + ac0];
            pa1 = *(const float4*)&Abase[(size_t)ar1 * D_ + k0 + ac1];
            pb0 = *(const float4*)&Wbase[(size_t)(k0 + br0) * D_ + bc0];
            pb1 = *(const float4*)&Wbase[(size_t)(k0 + br1) * D_ + bc1];
        }

        // --- 4 k-chunks of 8, 3 passes each (AhBh, AhBl, AlBh) ---
#pragma unroll
        for (int kc = 0; kc < 4; ++kc) {
            const int ko = kc * 8;
            uint32_t ah[2][4], bh[4][2];
#pragma unroll
            for (int t = 0; t < 2; ++t) {
                const int rm = wm + t * 16 + l4;
                ah[t][0] = f2u(Ah[rm * ASTR + ko + l2]);
                ah[t][1] = f2u(Ah[(rm + 8) * ASTR + ko + l2]);
                ah[t][2] = f2u(Ah[rm * ASTR + ko + l2 + 4]);
                ah[t][3] = f2u(Ah[(rm + 8) * ASTR + ko + l2 + 4]);
            }
#pragma unroll
            for (int n = 0; n < 4; ++n) {
                const int cn = wn + n * 8 + l4;
                bh[n][0] = f2u(Bh[(ko + l2) * BSTR + cn]);
                bh[n][1] = f2u(Bh[(ko + l2 + 4) * BSTR + cn]);
            }
#pragma unroll
            for (int t = 0; t < 2; ++t)
#pragma unroll
                for (int n = 0; n < 4; ++n)
                    mma_tf32(acc[t][n], ah[t], bh[n]);

            uint32_t bl[4][2];
#pragma unroll
            for (int n = 0; n < 4; ++n) {
                const int cn = wn + n * 8 + l4;
                bl[n][0] = f2u(Bl[(ko + l2) * BSTR + cn]);
                bl[n][1] = f2u(Bl[(ko + l2 + 4) * BSTR + cn]);
            }
#pragma unroll
            for (int t = 0; t < 2; ++t)
#pragma unroll
                for (int n = 0; n < 4; ++n)
                    mma_tf32(acc[t][n], ah[t], bl[n]);

            uint32_t al[2][4];
#pragma unroll
            for (int t = 0; t < 2; ++t) {
                const int rm = wm + t * 16 + l4;
                al[t][0] = f2u(Al[rm * ASTR + ko + l2]);
                al[t][1] = f2u(Al[(rm + 8) * ASTR + ko + l2]);
                al[t][2] = f2u(Al[rm * ASTR + ko + l2 + 4]);
                al[t][3] = f2u(Al[(rm + 8) * ASTR + ko + l2 + 4]);
            }
#pragma unroll
            for (int t = 0; t < 2; ++t)
#pragma unroll
                for (int n = 0; n < 4; ++n)
                    mma_tf32(acc[t][n], al[t], bh[n]);
        }
        __syncthreads();
    }

    // --- epilogue: registers -> gmem (float2 stores + bias) ---
#pragma unroll
    for (int n = 0; n < 4; ++n) {
        const int c = bx * 128 + wn + n * 8 + l2 * 2;
        const float b0 = bias[c];
        const float b1 = bias[c + 1];
#pragma unroll
        for (int t = 0; t < 2; ++t) {
            const int r0 = by * 128 + wm + t * 16 + l4;
            *(float2*)&C[(size_t)r0 * D_ + c] =
                make_float2(acc[t][n][0] + b0, acc[t][n][1] + b1);
            *(float2*)&C[(size_t)(r0 + 8) * D_ + c] =
                make_float2(acc[t][n][2] + b0, acc[t][n][3] + b1);
        }
    }
}

__global__ __launch_bounds__(512, 1) void qkv_mma_kernel(
    const float* __restrict__ x,
    const float* __restrict__ wq, const float* __restrict__ bq,
    const float* __restrict__ wk, const float* __restrict__ bk,
    const float* __restrict__ wv, const float* __restrict__ bv)
{
    const int z = blockIdx.z;
    const float* W  = (z == 0) ? wq : (z == 1) ? wk : wv;
    const float* bb = (z == 0) ? bq : (z == 1) ? bk : bv;
    float* C = (z == 0) ? g_q : (z == 1) ? g_k : g_v;
    tc_gemm(x, W, bb, C);
}

__global__ __launch_bounds__(512, 1) void proj_mma_kernel(
    const float* __restrict__ wp, const float* __restrict__ bp,
    float* __restrict__ out)
{
    tc_gemm(g_ctx, wp, bp, out);
}

// ---------------------------------------------------------------------------
// Flash attention (causal), Br = Bc = 64, HD = 128, fp32 (unchanged, passing)
// ---------------------------------------------------------------------------
#define KS_STRIDE 132
#define PS_STRIDE 65

__global__ __launch_bounds__(256, 1) void attn_kernel()
{
    extern __shared__ float sm[];
    float* Qs = sm;
    float* Ks = Qs + 64 * HD_;
    float* Vs = Ks + 64 * KS_STRIDE;
    float* Ps = Vs + 64 * HD_;

    const int tid = threadIdx.x;
    const int ty  = tid >> 4;
    const int tx  = tid & 15;

    const int qb = blockIdx.x;
    const int b  = blockIdx.y >> 4;
    const int h  = blockIdx.y & 15;

    const float* Qb = g_q + (size_t)b * S_ * D_ + (size_t)h * HD_;
    const float* Kb = g_k + (size_t)b * S_ * D_ + (size_t)h * HD_;
    const float* Vb = g_v + (size_t)b * S_ * D_ + (size_t)h * HD_;
    float*       Ob = g_ctx + (size_t)b * S_ * D_ + (size_t)h * HD_;

    for (int t = tid; t < 64 * 32; t += 256) {
        int r = t >> 5;
        int c = (t & 31) << 2;
        *(float4*)&Qs[r * HD_ + c] =
            *(const float4*)&Qb[(size_t)(qb * 64 + r) * D_ + c];
    }

    float acc[4][8];
#pragma unroll
    for (int i = 0; i < 4; i++)
#pragma unroll
        for (int j = 0; j < 8; j++) acc[i][j] = 0.0f;
    float mrow[4] = {-INFINITY, -INFINITY, -INFINITY, -INFINITY};
    float lrow[4] = {0.0f, 0.0f, 0.0f, 0.0f};

    const float scale = 0.08838834764831845f;

    __syncthreads();

    for (int kb = 0; kb <= qb; kb++) {
        for (int t = tid; t < 64 * 32; t += 256) {
            int r = t >> 5;
            int c = (t & 31) << 2;
            *(float4*)&Ks[r * KS_STRIDE + c] =
                *(const float4*)&Kb[(size_t)(kb * 64 + r) * D_ + c];
            *(float4*)&Vs[r * HD_ + c] =
                *(const float4*)&Vb[(size_t)(kb * 64 + r) * D_ + c];
        }
        __syncthreads();

        float s[4][4];
#pragma unroll
        for (int i = 0; i < 4; i++)
#pragma unroll
            for (int j = 0; j < 4; j++) s[i][j] = 0.0f;

#pragma unroll 4
        for (int kk = 0; kk < HD_; kk += 4) {
            float4 qv[4], kv[4];
#pragma unroll
            for (int i = 0; i < 4; i++)
                qv[i] = *(const float4*)&Qs[(4 * ty + i) * HD_ + kk];
#pragma unroll
            for (int j = 0; j < 4; j++)
                kv[j] = *(const float4*)&Ks[(tx + 16 * j) * KS_STRIDE + kk];
#pragma unroll
            for (int i = 0; i < 4; i++)
#pragma unroll
                for (int j = 0; j < 4; j++) {
                    s[i][j] += qv[i].x * kv[j].x;
                    s[i][j] += qv[i].y * kv[j].y;
                    s[i][j] += qv[i].z * kv[j].z;
                    s[i][j] += qv[i].w * kv[j].w;
                }
        }

        const bool diag = (kb == qb);
#pragma unroll
        for (int i = 0; i < 4; i++) {
            int qr = 4 * ty + i;
#pragma unroll
            for (int j = 0; j < 4; j++) {
                int kc = tx + 16 * j;
                float sv = s[i][j] * scale;
                if (diag && kc > qr) sv = -INFINITY;
                s[i][j] = sv;
            }
        }

#pragma unroll
        for (int i = 0; i < 4; i++) {
            float tmax = fmaxf(fmaxf(s[i][0], s[i][1]), fmaxf(s[i][2], s[i][3]));
#pragma unroll
            for (int o = 8; o >= 1; o >>= 1)
                tmax = fmaxf(tmax, __shfl_xor_sync(0xffffffffu, tmax, o));
            float mnew = fmaxf(mrow[i], tmax);
            float corr = __expf(mrow[i] - mnew);
            float rsum = 0.0f;
#pragma unroll
            for (int j = 0; j < 4; j++) {
                float p = __expf(s[i][j] - mnew);
                Ps[(4 * ty + i) * PS_STRIDE + tx + 16 * j] = p;
                rsum += p;
            }
#pragma unroll
            for (int o = 8; o >= 1; o >>= 1)
                rsum += __shfl_xor_sync(0xffffffffu, rsum, o);
            lrow[i] = lrow[i] * corr + rsum;
            mrow[i] = mnew;
#pragma unroll
            for (int j = 0; j < 8; j++) acc[i][j] *= corr;
        }
        __syncthreads();

#pragma unroll 4
        for (int k = 0; k < 64; k++) {
            float pv[4], vv[8];
#pragma unroll
            for (int i = 0; i < 4; i++)
                pv[i] = Ps[(4 * ty + i) * PS_STRIDE + k];
#pragma unroll
            for (int j = 0; j < 8; j++)
                vv[j] = Vs[k * HD_ + tx + 16 * j];
#pragma unroll
            for (int i = 0; i < 4; i++)
#pragma unroll
                for (int j = 0; j < 8; j++)
                    acc[i][j] += pv[i] * vv[j];
        }
        __syncthreads();
    }

#pragma unroll
    for (int i = 0; i < 4; i++) {
        float inv = 1.0f / lrow[i];
        size_t rowoff = (size_t)(qb * 64 + 4 * ty + i) * D_;
#pragma unroll
        for (int j = 0; j < 8; j++)
            Ob[rowoff + tx + 16 * j] = acc[i][j] * inv;
    }
}

// ---------------------------------------------------------------------------
// launch
// ---------------------------------------------------------------------------
extern "C" void kernel_launch(void* const* d_in, const int* in_sizes, int n_in,
                              void* d_out, int out_size)
{
    const float* x  = (const float*)d_in[0];
    const float* wq = (const float*)d_in[1];
    const float* bq = (const float*)d_in[2];
    const float* wk = (const float*)d_in[3];
    const float* bk = (const float*)d_in[4];
    const float* wv = (const float*)d_in[5];
    const float* bv = (const float*)d_in[6];
    const float* wp = (const float*)d_in[7];
    const float* bp = (const float*)d_in[8];
    float* out = (float*)d_out;

    cudaFuncSetAttribute(qkv_mma_kernel,
                         cudaFuncAttributeMaxDynamicSharedMemorySize, GEMM_SMEM);
    cudaFuncSetAttribute(proj_mma_kernel,
                         cudaFuncAttributeMaxDynamicSharedMemorySize, GEMM_SMEM);

    qkv_mma_kernel<<<dim3(D_ / 128, M_ / 128, 3), 512, GEMM_SMEM>>>(
        x, wq, bq, wk, bk, wv, bv);

    const int asmem = (64 * HD_ + 64 * KS_STRIDE + 64 * HD_ + 64 * PS_STRIDE) *
                      (int)sizeof(float);
    cudaFuncSetAttribute(attn_kernel,
                         cudaFuncAttributeMaxDynamicSharedMemorySize, asmem);
    attn_kernel<<<dim3(S_ / 64, B_ * H_), 256, asmem>>>();

    proj_mma_kernel<<<dim3(D_ / 128, M_ / 128), 512, GEMM_SMEM>>>(wp, bp, out);
}